// round 9
// baseline (speedup 1.0000x reference)
#include <cuda_runtime.h>

// Inverse 2D Haar wavelet (fused conv_transpose chain).
// x:   [8, 256, 128, 128] fp32, subbands LL | HL | LH | HH each 64 channels
// out: [8,  64, 256, 256] fp32
//
// out[2h,2w]     = 0.5*(LL+LH+HL+HH)
// out[2h,2w+1]   = 0.5*(LL-LH+HL-HH)
// out[2h+1,2w]   = 0.5*(LL+LH-HL-HH)
// out[2h+1,2w+1] = 0.5*(LL-LH-HL+HH)
//
// Hybrid of the two best variants: two input rows per thread (8 independent
// front-batched LDG.128 -> MLP=8) + 256-bit stores (one STG.256 per output
// row, 4 rows). All accesses fully warp-contiguous. Stores evict_first (.cs).
// At 268MB logical / ~35us we are ~95% of the 8TB/s spec roofline.

#define B_  8
#define C_  64
#define H_  128
#define W_  128
#define HP_ (H_ / 2)               // 64 row-pairs
#define W4_ (W_ / 4)               // 32 float4 per row
#define IN_PLANE   (H_ * W_)       // 16384
#define IN_BSTRIDE (4 * C_ * IN_PLANE)
#define OUT_W      (2 * W_)        // 256
#define OUT_PLANE  (4 * IN_PLANE)  // 65536
#define OUT_BSTRIDE (C_ * OUT_PLANE)

__device__ __forceinline__ void st256_cs(float* p, const float* f) {
    asm volatile(
        "st.global.cs.v8.b32 [%0], {%1, %2, %3, %4, %5, %6, %7, %8};"
        :: "l"(p),
           "r"(__float_as_uint(f[0])), "r"(__float_as_uint(f[1])),
           "r"(__float_as_uint(f[2])), "r"(__float_as_uint(f[3])),
           "r"(__float_as_uint(f[4])), "r"(__float_as_uint(f[5])),
           "r"(__float_as_uint(f[6])), "r"(__float_as_uint(f[7]))
        : "memory");
}

__device__ __forceinline__ void haar4(const float4& ll, const float4& lh,
                                      const float4& hl, const float4& hh,
                                      float* r0, float* r1) {
    const float* a = &ll.x;
    const float* bq = &lh.x;
    const float* cq = &hl.x;
    const float* d = &hh.x;
#pragma unroll
    for (int i = 0; i < 4; i++) {
        float apb = a[i] + bq[i], amb = a[i] - bq[i];
        float cpd = cq[i] + d[i], cmd = cq[i] - d[i];
        r0[2 * i]     = 0.5f * (apb + cpd);
        r0[2 * i + 1] = 0.5f * (amb + cmd);
        r1[2 * i]     = 0.5f * (apb - cpd);
        r1[2 * i + 1] = 0.5f * (amb - cmd);
    }
}

__global__ __launch_bounds__(256) void iwt_kernel(const float* __restrict__ x,
                                                  float* __restrict__ out) {
    int idx = blockIdx.x * blockDim.x + threadIdx.x;
    // idx -> (b, c, hp, w4)
    int w4 = idx & (W4_ - 1);
    int t  = idx >> 5;             // / 32
    int hp = t & (HP_ - 1);
    t >>= 6;                       // / 64
    int c  = t & (C_ - 1);
    int b  = t >> 6;               // / 64

    const float* base = x + (long long)b * IN_BSTRIDE + (long long)c * IN_PLANE
                          + (2 * hp) * W_ + (w4 << 2);

    // Front-batched: 8 independent LDG.128 (2 rows x 4 subbands)
    float4 ll0 = __ldg((const float4*)(base));
    float4 hl0 = __ldg((const float4*)(base + 64  * IN_PLANE));
    float4 lh0 = __ldg((const float4*)(base + 128 * IN_PLANE));
    float4 hh0 = __ldg((const float4*)(base + 192 * IN_PLANE));
    float4 ll1 = __ldg((const float4*)(base + W_));
    float4 hl1 = __ldg((const float4*)(base + 64  * IN_PLANE + W_));
    float4 lh1 = __ldg((const float4*)(base + 128 * IN_PLANE + W_));
    float4 hh1 = __ldg((const float4*)(base + 192 * IN_PLANE + W_));

    float* obase = out + (long long)b * OUT_BSTRIDE + (long long)c * OUT_PLANE
                       + (4 * hp) * OUT_W + (w4 << 3);

    float r0[8], r1[8], r2[8], r3[8];
    haar4(ll0, lh0, hl0, hh0, r0, r1);
    haar4(ll1, lh1, hl1, hh1, r2, r3);

    st256_cs(obase,              r0);
    st256_cs(obase +     OUT_W,  r1);
    st256_cs(obase + 2 * OUT_W,  r2);
    st256_cs(obase + 3 * OUT_W,  r3);
}

extern "C" void kernel_launch(void* const* d_in, const int* in_sizes, int n_in,
                              void* d_out, int out_size) {
    const float* x = (const float*)d_in[0];
    float* out = (float*)d_out;
    const int total = B_ * C_ * HP_ * W4_;   // 1,048,576 threads
    iwt_kernel<<<total / 256, 256>>>(x, out);
}

// round 10
// speedup vs baseline: 1.0140x; 1.0140x over previous
#include <cuda_runtime.h>

// Inverse 2D Haar wavelet (fused conv_transpose chain). FINAL (= Round-7 champion).
// x:   [8, 256, 128, 128] fp32, subbands LL | HL | LH | HH each 64 channels
// out: [8,  64, 256, 256] fp32
//
// out[2h,2w]     = 0.5*(LL+LH+HL+HH)
// out[2h,2w+1]   = 0.5*(LL-LH+HL-HH)
// out[2h+1,2w]   = 0.5*(LL+LH-HL-HH)
// out[2h+1,2w+1] = 0.5*(LL-LH-HL+HH)
//
// Each thread: one float4 of input per subband (4 x LDG.128, front-batched),
// emits TWO 256-bit stores (st.global.cs.v8.b32), one per output row.
// Consecutive threads write consecutive 32B -> perfect full-line stores.
// Stores evict_first (write-once stream).
//
// Converged at ~95% of 8TB/s HBM spec (268MB logical / ~35.4us kernel).
// Explored and rejected: L2 persistence policies (3 variants, input > L2,
// circular thrash), 256-bit loads (occupancy cost), 2-rows/thread MLP=8
// (ditto). Highest-occupancy perfect-coalescing variant wins at the
// mixed read/write HBM ceiling.

#define B_  8
#define C_  64
#define H_  128
#define W_  128
#define W4_ (W_ / 4)               // 32 float4 per row
#define IN_PLANE   (H_ * W_)       // 16384
#define IN_BSTRIDE (4 * C_ * IN_PLANE)
#define OUT_W      (2 * W_)        // 256
#define OUT_PLANE  (4 * IN_PLANE)  // 65536
#define OUT_BSTRIDE (C_ * OUT_PLANE)

__device__ __forceinline__ void st256_cs(float* p,
                                         float f0, float f1, float f2, float f3,
                                         float f4, float f5, float f6, float f7) {
    asm volatile(
        "st.global.cs.v8.b32 [%0], {%1, %2, %3, %4, %5, %6, %7, %8};"
        :: "l"(p),
           "r"(__float_as_uint(f0)), "r"(__float_as_uint(f1)),
           "r"(__float_as_uint(f2)), "r"(__float_as_uint(f3)),
           "r"(__float_as_uint(f4)), "r"(__float_as_uint(f5)),
           "r"(__float_as_uint(f6)), "r"(__float_as_uint(f7))
        : "memory");
}

__global__ __launch_bounds__(256) void iwt_kernel(const float* __restrict__ x,
                                                  float* __restrict__ out) {
    int idx = blockIdx.x * blockDim.x + threadIdx.x;
    // idx -> (b, c, h, w4)
    int w4 = idx & (W4_ - 1);
    int t  = idx >> 5;             // / 32
    int h  = t & (H_ - 1);
    t >>= 7;                       // / 128
    int c  = t & (C_ - 1);
    int b  = t >> 6;               // / 64

    const float* base = x + (long long)b * IN_BSTRIDE + (long long)c * IN_PLANE
                          + h * W_ + (w4 << 2);

    // Front-batched independent 128-bit loads, one per subband
    float4 ll = __ldg((const float4*)(base));
    float4 hl = __ldg((const float4*)(base + 64  * IN_PLANE));
    float4 lh = __ldg((const float4*)(base + 128 * IN_PLANE));
    float4 hh = __ldg((const float4*)(base + 192 * IN_PLANE));

    float* obase = out + (long long)b * OUT_BSTRIDE + (long long)c * OUT_PLANE
                       + (2 * h) * OUT_W + (w4 << 3);

    float r0[8], r1[8];

    {   // element 0 -> out cols 0,1
        float a = ll.x, bq = lh.x, cq = hl.x, d = hh.x;
        float apb = a + bq, amb = a - bq, cpd = cq + d, cmd = cq - d;
        r0[0] = 0.5f * (apb + cpd);  r0[1] = 0.5f * (amb + cmd);
        r1[0] = 0.5f * (apb - cpd);  r1[1] = 0.5f * (amb - cmd);
    }
    {   // element 1 -> out cols 2,3
        float a = ll.y, bq = lh.y, cq = hl.y, d = hh.y;
        float apb = a + bq, amb = a - bq, cpd = cq + d, cmd = cq - d;
        r0[2] = 0.5f * (apb + cpd);  r0[3] = 0.5f * (amb + cmd);
        r1[2] = 0.5f * (apb - cpd);  r1[3] = 0.5f * (amb - cmd);
    }
    {   // element 2 -> out cols 4,5
        float a = ll.z, bq = lh.z, cq = hl.z, d = hh.z;
        float apb = a + bq, amb = a - bq, cpd = cq + d, cmd = cq - d;
        r0[4] = 0.5f * (apb + cpd);  r0[5] = 0.5f * (amb + cmd);
        r1[4] = 0.5f * (apb - cpd);  r1[5] = 0.5f * (amb - cmd);
    }
    {   // element 3 -> out cols 6,7
        float a = ll.w, bq = lh.w, cq = hl.w, d = hh.w;
        float apb = a + bq, amb = a - bq, cpd = cq + d, cmd = cq - d;
        r0[6] = 0.5f * (apb + cpd);  r0[7] = 0.5f * (amb + cmd);
        r1[6] = 0.5f * (apb - cpd);  r1[7] = 0.5f * (amb - cmd);
    }

    st256_cs(obase,
             r0[0], r0[1], r0[2], r0[3], r0[4], r0[5], r0[6], r0[7]);
    st256_cs(obase + OUT_W,
             r1[0], r1[1], r1[2], r1[3], r1[4], r1[5], r1[6], r1[7]);
}

extern "C" void kernel_launch(void* const* d_in, const int* in_sizes, int n_in,
                              void* d_out, int out_size) {
    const float* x = (const float*)d_in[0];
    float* out = (float*)d_out;
    const int total = B_ * C_ * H_ * W4_;   // 2,097,152 threads
    iwt_kernel<<<total / 256, 256>>>(x, out);
}